// round 4
// baseline (speedup 1.0000x reference)
#include <cuda_runtime.h>
#include <cstdint>
#include <cstdio>

#define HDIM 64

static const int NMAX = 100000;
static const int EMAX = 1600000;
static const int SCANB = 1024;
static const int NBLK = (NMAX + SCANB - 1) / SCANB;   // 98

// ---------------- device scratch (allocation-free rule) ----------------
__device__ __align__(16) int   g_cnt[NMAX];
__device__ __align__(16) int   g_rowptr[NMAX];
__device__ __align__(16) int   g_cursor[NMAX];
__device__ __align__(16) int   g_bsum[NBLK];
__device__ __align__(16) int   g_boff[NBLK];
__device__ __align__(16) float g_dinv[NMAX];
__device__ __align__(16) int2  g_csr[EMAX];           // {src, norm bits}
__device__ __align__(16) float g_ht[(size_t)NMAX * HDIM];
__device__ __align__(16) float g_bufA[(size_t)NMAX * HDIM];
__device__ __align__(16) float g_bufB[(size_t)NMAX * HDIM];

// ---------------- prep: degree histogram, dinv, scan, CSR scatter ----------------
__global__ void zero_cnt_kernel(int N) {
    int i = blockIdx.x * blockDim.x + threadIdx.x;
    if (i < N) g_cnt[i] = 0;
}

__global__ void hist_kernel(const int* __restrict__ ei, int E) {
    int e = blockIdx.x * blockDim.x + threadIdx.x;
    if (e >= E) return;
    atomicAdd(&g_cnt[ei[(size_t)E + e]], 1);
}

// block-level inclusive scan -> exclusive partials + block sums; also dinv
__global__ void scan1_kernel(int N) {
    __shared__ int s[SCANB];
    int t = threadIdx.x;
    int i = blockIdx.x * SCANB + t;
    int v = (i < N) ? g_cnt[i] : 0;
    if (i < N) g_dinv[i] = rsqrtf((float)v + 1.0f);  // +1 = self loop
    s[t] = v;
    __syncthreads();
#pragma unroll
    for (int off = 1; off < SCANB; off <<= 1) {
        int a = (t >= off) ? s[t - off] : 0;
        __syncthreads();
        s[t] += a;
        __syncthreads();
    }
    if (i < N) g_rowptr[i] = s[t] - v;   // exclusive
    if (t == SCANB - 1) g_bsum[blockIdx.x] = s[t];
}

// single-block parallel scan of block sums (nb <= 128)
__global__ void scan2_kernel(int nb) {
    __shared__ int s[128];
    int t = threadIdx.x;
    int v = (t < nb) ? g_bsum[t] : 0;
    s[t] = v;
    __syncthreads();
#pragma unroll
    for (int off = 1; off < 128; off <<= 1) {
        int a = (t >= off) ? s[t - off] : 0;
        __syncthreads();
        s[t] += a;
        __syncthreads();
    }
    if (t < nb) g_boff[t] = s[t] - v;    // exclusive
}

__global__ void scan3_kernel(int N) {
    int i = blockIdx.x * blockDim.x + threadIdx.x;
    if (i >= N) return;
    int r = g_rowptr[i] + g_boff[i >> 10];
    g_rowptr[i] = r;
    g_cursor[i] = r;
}

__global__ void scatter_csr_kernel(const int* __restrict__ ei, int E) {
    int e = blockIdx.x * blockDim.x + threadIdx.x;
    if (e >= E) return;
    int s = ei[e];
    int d = ei[(size_t)E + e];
    int pos = atomicAdd(&g_cursor[d], 1);
    float nrm = g_dinv[s] * g_dinv[d];
    g_csr[pos] = make_int2(s, __float_as_int(nrm));
}

// ---------------- GEMM: HT = act(X) @ W  (row-paired fp32x2 FMA)
// 64 rows x 64 cols per block, 128 threads; thread tile 8 rows x 4 cols.
// Accumulator pairs are row-pairs -> x pairs come straight from Xs as LDS.128;
// W is pre-duplicated {w,w} in shared.
template <int DIN, bool RELU_IN>
__global__ void __launch_bounds__(128) gemm_kernel(const float* __restrict__ X,
                                                   const float* __restrict__ W,
                                                   float* __restrict__ HT,
                                                   int N) {
    __shared__ __align__(16) float Xs[16][68];   // k x row, stride 68 (16B aligned, low conflict)
    __shared__ __align__(16) float2 Wd[16][64];  // k x col, duplicated

    const int t  = threadIdx.x;       // 0..127
    const int cg = t & 15;            // cols cg*4 .. cg*4+3
    const int rg = t >> 4;            // rows rg*8 .. rg*8+7
    const int row0 = blockIdx.x * 64;

    unsigned long long acc[4][4];     // [col j][row pair p]
#pragma unroll
    for (int j = 0; j < 4; j++)
#pragma unroll
        for (int p = 0; p < 4; p++) acc[j][p] = 0ull;

    for (int k0 = 0; k0 < DIN; k0 += 16) {
        // load X tile: 64 rows x 16 k (2 float4 per thread), transposed store
#pragma unroll
        for (int l = 0; l < 2; l++) {
            int idx = t + l * 128;            // 0..255
            int r   = idx >> 2;               // 0..63
            int kk  = (idx & 3) * 4;
            int grow = row0 + r;
            float4 v = make_float4(0.f, 0.f, 0.f, 0.f);
            if (grow < N)
                v = *(const float4*)&X[(size_t)grow * DIN + k0 + kk];
            if (RELU_IN) {
                v.x = fmaxf(v.x, 0.f); v.y = fmaxf(v.y, 0.f);
                v.z = fmaxf(v.z, 0.f); v.w = fmaxf(v.w, 0.f);
            }
            Xs[kk + 0][r] = v.x;
            Xs[kk + 1][r] = v.y;
            Xs[kk + 2][r] = v.z;
            Xs[kk + 3][r] = v.w;
        }
        // load W tile 16x64 duplicated (2 float4 per thread)
#pragma unroll
        for (int l = 0; l < 2; l++) {
            int idx = t + l * 128;            // 0..255 float4 units
            int kk  = idx >> 4;               // 0..15
            int c   = (idx & 15) * 4;
            float4 w = *(const float4*)&W[(size_t)(k0 + kk) * HDIM + c];
            Wd[kk][c + 0] = make_float2(w.x, w.x);
            Wd[kk][c + 1] = make_float2(w.y, w.y);
            Wd[kk][c + 2] = make_float2(w.z, w.z);
            Wd[kk][c + 3] = make_float2(w.w, w.w);
        }
        __syncthreads();

#pragma unroll
        for (int kk = 0; kk < 16; kk++) {
            // 8 consecutive rows = 4 packed f32x2 pairs (two 16B loads)
            ulonglong2 xa = *(const ulonglong2*)&Xs[kk][rg * 8];      // pairs p=0,1
            ulonglong2 xb = *(const ulonglong2*)&Xs[kk][rg * 8 + 4];  // pairs p=2,3
            // 4 duplicated w values (two 16B loads)
            ulonglong2 wa = *(const ulonglong2*)&Wd[kk][cg * 4];      // cols j=0,1
            ulonglong2 wb = *(const ulonglong2*)&Wd[kk][cg * 4 + 2];  // cols j=2,3
            unsigned long long xp[4] = {xa.x, xa.y, xb.x, xb.y};
            unsigned long long wp[4] = {wa.x, wa.y, wb.x, wb.y};
#pragma unroll
            for (int j = 0; j < 4; j++)
#pragma unroll
                for (int p = 0; p < 4; p++)
                    asm("fma.rn.f32x2 %0, %1, %2, %0;"
                        : "+l"(acc[j][p]) : "l"(xp[p]), "l"(wp[j]));
        }
        __syncthreads();
    }

    // epilogue: each acc pair holds rows (rg*8+2p, rg*8+2p+1) for col cg*4+j
#pragma unroll
    for (int p = 0; p < 4; p++) {
        unsigned int lo[4], hi[4];
#pragma unroll
        for (int j = 0; j < 4; j++)
            asm("mov.b64 {%0, %1}, %2;" : "=r"(lo[j]), "=r"(hi[j]) : "l"(acc[j][p]));
        int r0 = row0 + rg * 8 + 2 * p;
        if (r0 < N) {
            float4 hv = make_float4(__uint_as_float(lo[0]), __uint_as_float(lo[1]),
                                    __uint_as_float(lo[2]), __uint_as_float(lo[3]));
            *(float4*)&HT[(size_t)r0 * HDIM + cg * 4] = hv;
        }
        if (r0 + 1 < N) {
            float4 hv = make_float4(__uint_as_float(hi[0]), __uint_as_float(hi[1]),
                                    __uint_as_float(hi[2]), __uint_as_float(hi[3]));
            *(float4*)&HT[(size_t)(r0 + 1) * HDIM + cg * 4] = hv;
        }
    }
}

// ---------------- aggregate: OUT[d] = bias + HT[d]*dinv[d]^2 + sum_e HT[src_e]*norm_e
// 16 threads per node, each owns one float4 of the 64-wide row.
__global__ void aggregate_kernel(const float* __restrict__ HT,
                                 const float* __restrict__ bias,
                                 float* __restrict__ OUT,
                                 int N) {
    int idx  = blockIdx.x * blockDim.x + threadIdx.x;
    int node = idx >> 4;
    int lane = idx & 15;
    if (node >= N) return;

    int start = g_rowptr[node];
    int cnt   = g_cnt[node];

    float4 a0 = make_float4(0.f, 0.f, 0.f, 0.f);
    float4 a1 = make_float4(0.f, 0.f, 0.f, 0.f);
    float4 a2 = make_float4(0.f, 0.f, 0.f, 0.f);
    float4 a3 = make_float4(0.f, 0.f, 0.f, 0.f);

    int i = 0;
    for (; i + 4 <= cnt; i += 4) {
        int2 c0 = __ldg(&g_csr[start + i + 0]);
        int2 c1 = __ldg(&g_csr[start + i + 1]);
        int2 c2 = __ldg(&g_csr[start + i + 2]);
        int2 c3 = __ldg(&g_csr[start + i + 3]);
        float4 v0 = __ldg((const float4*)&HT[(size_t)c0.x * HDIM + lane * 4]);
        float4 v1 = __ldg((const float4*)&HT[(size_t)c1.x * HDIM + lane * 4]);
        float4 v2 = __ldg((const float4*)&HT[(size_t)c2.x * HDIM + lane * 4]);
        float4 v3 = __ldg((const float4*)&HT[(size_t)c3.x * HDIM + lane * 4]);
        float n0 = __int_as_float(c0.y), n1 = __int_as_float(c1.y);
        float n2 = __int_as_float(c2.y), n3 = __int_as_float(c3.y);
        a0.x += v0.x * n0; a0.y += v0.y * n0; a0.z += v0.z * n0; a0.w += v0.w * n0;
        a1.x += v1.x * n1; a1.y += v1.y * n1; a1.z += v1.z * n1; a1.w += v1.w * n1;
        a2.x += v2.x * n2; a2.y += v2.y * n2; a2.z += v2.z * n2; a2.w += v2.w * n2;
        a3.x += v3.x * n3; a3.y += v3.y * n3; a3.z += v3.z * n3; a3.w += v3.w * n3;
    }
    for (; i < cnt; i++) {
        int2 c0 = __ldg(&g_csr[start + i]);
        float4 v0 = __ldg((const float4*)&HT[(size_t)c0.x * HDIM + lane * 4]);
        float n0 = __int_as_float(c0.y);
        a0.x += v0.x * n0; a0.y += v0.y * n0; a0.z += v0.z * n0; a0.w += v0.w * n0;
    }
    a0.x += a1.x; a0.y += a1.y; a0.z += a1.z; a0.w += a1.w;
    a2.x += a3.x; a2.y += a3.y; a2.z += a3.z; a2.w += a3.w;
    a0.x += a2.x; a0.y += a2.y; a0.z += a2.z; a0.w += a2.w;

    float di = g_dinv[node];
    float d2 = di * di;
    float4 h  = *(const float4*)&HT[(size_t)node * HDIM + lane * 4];
    float4 bb = *(const float4*)&bias[lane * 4];
    float4 o;
    o.x = bb.x + h.x * d2 + a0.x;
    o.y = bb.y + h.y * d2 + a0.y;
    o.z = bb.z + h.z * d2 + a0.z;
    o.w = bb.w + h.w * d2 + a0.w;
    *(float4*)&OUT[(size_t)node * HDIM + lane * 4] = o;
}

// ---------------- final FC (64->2) + log_softmax ----------------
__global__ void fc_kernel(const float* __restrict__ Hin,
                          const float* __restrict__ Wfc,
                          const float* __restrict__ bfc,
                          float* __restrict__ out,
                          int N) {
    __shared__ float Wf[HDIM * 2];
    __shared__ float bf[2];
    if (threadIdx.x < HDIM * 2) Wf[threadIdx.x] = Wfc[threadIdx.x];
    if (threadIdx.x < 2) bf[threadIdx.x] = bfc[threadIdx.x];
    __syncthreads();

    int n = blockIdx.x * blockDim.x + threadIdx.x;
    if (n >= N) return;

    float l0 = bf[0], l1 = bf[1];
    const float4* hp = (const float4*)&Hin[(size_t)n * HDIM];
#pragma unroll
    for (int k4 = 0; k4 < HDIM / 4; k4++) {
        float4 h = hp[k4];
        float h0 = fmaxf(h.x, 0.f), h1 = fmaxf(h.y, 0.f);
        float h2 = fmaxf(h.z, 0.f), h3 = fmaxf(h.w, 0.f);
        int k = k4 * 4;
        l0 += h0 * Wf[(k + 0) * 2 + 0] + h1 * Wf[(k + 1) * 2 + 0] +
              h2 * Wf[(k + 2) * 2 + 0] + h3 * Wf[(k + 3) * 2 + 0];
        l1 += h0 * Wf[(k + 0) * 2 + 1] + h1 * Wf[(k + 1) * 2 + 1] +
              h2 * Wf[(k + 2) * 2 + 1] + h3 * Wf[(k + 3) * 2 + 1];
    }
    float m = fmaxf(l0, l1);
    float lse = m + logf(expf(l0 - m) + expf(l1 - m));
    out[(size_t)n * 2 + 0] = l0 - lse;
    out[(size_t)n * 2 + 1] = l1 - lse;
}

// ---------------- launch ----------------
extern "C" void kernel_launch(void* const* d_in, const int* in_sizes, int n_in,
                              void* d_out, int out_size) {
    const float* x   = (const float*)d_in[0];
    const int*   ei  = (const int*)d_in[1];   // int32 (JAX x64 disabled)
    const float* W1  = (const float*)d_in[2];
    const float* b1  = (const float*)d_in[3];
    const float* W2  = (const float*)d_in[4];
    const float* b2  = (const float*)d_in[5];
    const float* W3  = (const float*)d_in[6];
    const float* b3  = (const float*)d_in[7];
    const float* Wfc = (const float*)d_in[8];
    const float* bfc = (const float*)d_in[9];

    const int Hh = in_sizes[3];            // 64
    const int D  = in_sizes[2] / Hh;       // 128
    const int N  = in_sizes[0] / D;        // 100000
    const int E  = in_sizes[1] / 2;        // 1600000

    float *ht, *bufA, *bufB;
    cudaGetSymbolAddress((void**)&ht,   g_ht);
    cudaGetSymbolAddress((void**)&bufA, g_bufA);
    cudaGetSymbolAddress((void**)&bufB, g_bufB);

    const int nb = (N + SCANB - 1) / SCANB;

    // CSR build
    zero_cnt_kernel<<<(N + 255) / 256, 256>>>(N);
    hist_kernel<<<(E + 255) / 256, 256>>>(ei, E);
    scan1_kernel<<<nb, SCANB>>>(N);
    scan2_kernel<<<1, 128>>>(nb);
    scan3_kernel<<<(N + 255) / 256, 256>>>(N);
    scatter_csr_kernel<<<(E + 255) / 256, 256>>>(ei, E);

    const int gblocks = (N + 63) / 64;
    const int ablocks = (N * 16 + 255) / 256;

    // layer 1
    gemm_kernel<128, false><<<gblocks, 128>>>(x, W1, ht, N);
    aggregate_kernel<<<ablocks, 256>>>(ht, b1, bufA, N);
    // layer 2
    gemm_kernel<64, true><<<gblocks, 128>>>(bufA, W2, ht, N);
    aggregate_kernel<<<ablocks, 256>>>(ht, b2, bufB, N);
    // layer 3
    gemm_kernel<64, true><<<gblocks, 128>>>(bufB, W3, ht, N);
    aggregate_kernel<<<ablocks, 256>>>(ht, b3, bufA, N);

    // final FC + log_softmax
    fc_kernel<<<(N + 127) / 128, 128>>>(bufA, Wfc, bfc, (float*)d_out, N);
}

// round 5
// speedup vs baseline: 1.1439x; 1.1439x over previous
#include <cuda_runtime.h>
#include <cstdint>
#include <cstdio>

#define HDIM 64

static const int NMAX = 100000;
static const int EMAX = 1600000;
static const int SCANB = 1024;
static const int NBLK = (NMAX + SCANB - 1) / SCANB;   // 98

// ---------------- device scratch (allocation-free rule) ----------------
__device__ __align__(16) int   g_cnt[NMAX];
__device__ __align__(16) int   g_rowptr[NMAX];
__device__ __align__(16) int   g_cursor[NMAX];
__device__ __align__(16) int   g_bsum[NBLK];
__device__ __align__(16) int   g_boff[NBLK];
__device__ __align__(16) float g_dinv[NMAX];
__device__ __align__(16) int2  g_csr[EMAX];           // {src, norm bits}
__device__ __align__(16) float g_ht[(size_t)NMAX * HDIM];
__device__ __align__(16) float g_bufA[(size_t)NMAX * HDIM];
__device__ __align__(16) float g_bufB[(size_t)NMAX * HDIM];

// ---------------- prep: degree histogram, dinv, scan, CSR scatter ----------------
__global__ void hist_kernel(const int* __restrict__ ei, int E) {
    int e = blockIdx.x * blockDim.x + threadIdx.x;
    if (e >= E) return;
    atomicAdd(&g_cnt[ei[(size_t)E + e]], 1);
}

// block-level inclusive scan -> exclusive partials + block sums; also dinv
__global__ void scan1_kernel(int N) {
    __shared__ int s[SCANB];
    int t = threadIdx.x;
    int i = blockIdx.x * SCANB + t;
    int v = (i < N) ? g_cnt[i] : 0;
    if (i < N) g_dinv[i] = rsqrtf((float)v + 1.0f);  // +1 = self loop
    s[t] = v;
    __syncthreads();
#pragma unroll
    for (int off = 1; off < SCANB; off <<= 1) {
        int a = (t >= off) ? s[t - off] : 0;
        __syncthreads();
        s[t] += a;
        __syncthreads();
    }
    if (i < N) g_rowptr[i] = s[t] - v;   // exclusive
    if (t == SCANB - 1) g_bsum[blockIdx.x] = s[t];
}

// single-block parallel scan of block sums (nb <= 128)
__global__ void scan2_kernel(int nb) {
    __shared__ int s[128];
    int t = threadIdx.x;
    int v = (t < nb) ? g_bsum[t] : 0;
    s[t] = v;
    __syncthreads();
#pragma unroll
    for (int off = 1; off < 128; off <<= 1) {
        int a = (t >= off) ? s[t - off] : 0;
        __syncthreads();
        s[t] += a;
        __syncthreads();
    }
    if (t < nb) g_boff[t] = s[t] - v;    // exclusive
}

__global__ void scan3_kernel(int N) {
    int i = blockIdx.x * blockDim.x + threadIdx.x;
    if (i >= N) return;
    int r = g_rowptr[i] + g_boff[i >> 10];
    g_rowptr[i] = r;
    g_cursor[i] = r;
}

__global__ void scatter_csr_kernel(const int* __restrict__ ei, int E) {
    int e = blockIdx.x * blockDim.x + threadIdx.x;
    if (e >= E) return;
    int s = ei[e];
    int d = ei[(size_t)E + e];
    int pos = atomicAdd(&g_cursor[d], 1);
    float nrm = g_dinv[s] * g_dinv[d];
    g_csr[pos] = make_int2(s, __float_as_int(nrm));
}

// ---------------- GEMM: HT = act(X) @ W  (packed fp32x2 FMA, col-pair form)
// BM=32 rows x 64 cols per block, 128 threads, 4 rows x 8 cols (4 f32x2 pairs) each.
// (Round-3 proven version.)
template <int DIN, bool RELU_IN>
__global__ void __launch_bounds__(128) gemm_kernel(const float* __restrict__ X,
                                                   const float* __restrict__ W,
                                                   float* __restrict__ HT,
                                                   int N) {
    __shared__ __align__(16) float Xs[16][32];
    __shared__ __align__(16) float Ws[16][64];

    const int t   = threadIdx.x;      // 0..127
    const int rg  = t >> 4;           // 0..7  (row group of 4)
    const int cg  = t & 15;           // 0..15 (col group of 4)
    const int row0 = blockIdx.x * 32;

    unsigned long long acc2[4][2];
#pragma unroll
    for (int i = 0; i < 4; i++) { acc2[i][0] = 0ull; acc2[i][1] = 0ull; }

    for (int k0 = 0; k0 < DIN; k0 += 16) {
        // load X tile: 32 rows x 16 k (each thread: one float4)
        {
            int r  = t >> 2;          // 0..31
            int kk = (t & 3) * 4;     // 0,4,8,12
            int grow = row0 + r;
            float4 v = make_float4(0.f, 0.f, 0.f, 0.f);
            if (grow < N)
                v = *(const float4*)&X[(size_t)grow * DIN + k0 + kk];
            if (RELU_IN) {
                v.x = fmaxf(v.x, 0.f); v.y = fmaxf(v.y, 0.f);
                v.z = fmaxf(v.z, 0.f); v.w = fmaxf(v.w, 0.f);
            }
            Xs[kk + 0][r] = v.x;
            Xs[kk + 1][r] = v.y;
            Xs[kk + 2][r] = v.z;
            Xs[kk + 3][r] = v.w;
        }
        // load W tile: 16 x 64 floats (each thread: two float4)
        {
#pragma unroll
            for (int i = 0; i < 2; i++) {
                int idx = t + i * 128;        // float4 index, 0..255
                int kk  = idx >> 4;           // 0..15
                int c   = (idx & 15) * 4;     // 0..60
                float4 w = *(const float4*)&W[(size_t)(k0 + kk) * HDIM + c];
                *(float4*)&Ws[kk][c] = w;
            }
        }
        __syncthreads();

#pragma unroll
        for (int kk = 0; kk < 16; kk++) {
            float4 xv = *(const float4*)&Xs[kk][rg * 4];
            ulonglong2 wv = *(const ulonglong2*)&Ws[kk][cg * 4]; // {w0,w1},{w2,w3}
            unsigned int xb[4] = {__float_as_uint(xv.x), __float_as_uint(xv.y),
                                  __float_as_uint(xv.z), __float_as_uint(xv.w)};
#pragma unroll
            for (int i = 0; i < 4; i++) {
                unsigned long long xp;
                asm("mov.b64 %0, {%1, %1};" : "=l"(xp) : "r"(xb[i]));
                asm("fma.rn.f32x2 %0, %1, %2, %0;" : "+l"(acc2[i][0]) : "l"(xp), "l"(wv.x));
                asm("fma.rn.f32x2 %0, %1, %2, %0;" : "+l"(acc2[i][1]) : "l"(xp), "l"(wv.y));
            }
        }
        __syncthreads();
    }

    // epilogue: write HT
#pragma unroll
    for (int i = 0; i < 4; i++) {
        int grow = row0 + rg * 4 + i;
        if (grow < N) {
            unsigned int u0, u1, u2, u3;
            asm("mov.b64 {%0, %1}, %2;" : "=r"(u0), "=r"(u1) : "l"(acc2[i][0]));
            asm("mov.b64 {%0, %1}, %2;" : "=r"(u2), "=r"(u3) : "l"(acc2[i][1]));
            float4 hv = make_float4(__uint_as_float(u0), __uint_as_float(u1),
                                    __uint_as_float(u2), __uint_as_float(u3));
            *(float4*)&HT[(size_t)grow * HDIM + cg * 4] = hv;
        }
    }
}

// ---------------- aggregate: OUT[d] = bias + HT[d]*dinv[d]^2 + sum_e HT[src_e]*norm_e
// 16 threads per node, each owns one float4 of the 64-wide row.
__global__ void aggregate_kernel(const float* __restrict__ HT,
                                 const float* __restrict__ bias,
                                 float* __restrict__ OUT,
                                 int N) {
    int idx  = blockIdx.x * blockDim.x + threadIdx.x;
    int node = idx >> 4;
    int lane = idx & 15;
    if (node >= N) return;

    int start = g_rowptr[node];
    int cnt   = g_cnt[node];

    float4 a0 = make_float4(0.f, 0.f, 0.f, 0.f);
    float4 a1 = make_float4(0.f, 0.f, 0.f, 0.f);
    float4 a2 = make_float4(0.f, 0.f, 0.f, 0.f);
    float4 a3 = make_float4(0.f, 0.f, 0.f, 0.f);

    int i = 0;
    for (; i + 4 <= cnt; i += 4) {
        int2 c0 = __ldg(&g_csr[start + i + 0]);
        int2 c1 = __ldg(&g_csr[start + i + 1]);
        int2 c2 = __ldg(&g_csr[start + i + 2]);
        int2 c3 = __ldg(&g_csr[start + i + 3]);
        float4 v0 = __ldg((const float4*)&HT[(size_t)c0.x * HDIM + lane * 4]);
        float4 v1 = __ldg((const float4*)&HT[(size_t)c1.x * HDIM + lane * 4]);
        float4 v2 = __ldg((const float4*)&HT[(size_t)c2.x * HDIM + lane * 4]);
        float4 v3 = __ldg((const float4*)&HT[(size_t)c3.x * HDIM + lane * 4]);
        float n0 = __int_as_float(c0.y), n1 = __int_as_float(c1.y);
        float n2 = __int_as_float(c2.y), n3 = __int_as_float(c3.y);
        a0.x += v0.x * n0; a0.y += v0.y * n0; a0.z += v0.z * n0; a0.w += v0.w * n0;
        a1.x += v1.x * n1; a1.y += v1.y * n1; a1.z += v1.z * n1; a1.w += v1.w * n1;
        a2.x += v2.x * n2; a2.y += v2.y * n2; a2.z += v2.z * n2; a2.w += v2.w * n2;
        a3.x += v3.x * n3; a3.y += v3.y * n3; a3.z += v3.z * n3; a3.w += v3.w * n3;
    }
    for (; i < cnt; i++) {
        int2 c0 = __ldg(&g_csr[start + i]);
        float4 v0 = __ldg((const float4*)&HT[(size_t)c0.x * HDIM + lane * 4]);
        float n0 = __int_as_float(c0.y);
        a0.x += v0.x * n0; a0.y += v0.y * n0; a0.z += v0.z * n0; a0.w += v0.w * n0;
    }
    a0.x += a1.x; a0.y += a1.y; a0.z += a1.z; a0.w += a1.w;
    a2.x += a3.x; a2.y += a3.y; a2.z += a3.z; a2.w += a3.w;
    a0.x += a2.x; a0.y += a2.y; a0.z += a2.z; a0.w += a2.w;

    float di = g_dinv[node];
    float d2 = di * di;
    float4 h  = *(const float4*)&HT[(size_t)node * HDIM + lane * 4];
    float4 bb = *(const float4*)&bias[lane * 4];
    float4 o;
    o.x = bb.x + h.x * d2 + a0.x;
    o.y = bb.y + h.y * d2 + a0.y;
    o.z = bb.z + h.z * d2 + a0.z;
    o.w = bb.w + h.w * d2 + a0.w;
    *(float4*)&OUT[(size_t)node * HDIM + lane * 4] = o;
}

// ---------------- final FC (64->2) + log_softmax ----------------
__global__ void fc_kernel(const float* __restrict__ Hin,
                          const float* __restrict__ Wfc,
                          const float* __restrict__ bfc,
                          float* __restrict__ out,
                          int N) {
    __shared__ float Wf[HDIM * 2];
    __shared__ float bf[2];
    if (threadIdx.x < HDIM * 2) Wf[threadIdx.x] = Wfc[threadIdx.x];
    if (threadIdx.x < 2) bf[threadIdx.x] = bfc[threadIdx.x];
    __syncthreads();

    int n = blockIdx.x * blockDim.x + threadIdx.x;
    if (n >= N) return;

    float l0 = bf[0], l1 = bf[1];
    const float4* hp = (const float4*)&Hin[(size_t)n * HDIM];
#pragma unroll
    for (int k4 = 0; k4 < HDIM / 4; k4++) {
        float4 h = hp[k4];
        float h0 = fmaxf(h.x, 0.f), h1 = fmaxf(h.y, 0.f);
        float h2 = fmaxf(h.z, 0.f), h3 = fmaxf(h.w, 0.f);
        int k = k4 * 4;
        l0 += h0 * Wf[(k + 0) * 2 + 0] + h1 * Wf[(k + 1) * 2 + 0] +
              h2 * Wf[(k + 2) * 2 + 0] + h3 * Wf[(k + 3) * 2 + 0];
        l1 += h0 * Wf[(k + 0) * 2 + 1] + h1 * Wf[(k + 1) * 2 + 1] +
              h2 * Wf[(k + 2) * 2 + 1] + h3 * Wf[(k + 3) * 2 + 1];
    }
    float m = fmaxf(l0, l1);
    float lse = m + logf(expf(l0 - m) + expf(l1 - m));
    out[(size_t)n * 2 + 0] = l0 - lse;
    out[(size_t)n * 2 + 1] = l1 - lse;
}

// ---------------- launch ----------------
extern "C" void kernel_launch(void* const* d_in, const int* in_sizes, int n_in,
                              void* d_out, int out_size) {
    const float* x   = (const float*)d_in[0];
    const int*   ei  = (const int*)d_in[1];   // int32 (JAX x64 disabled)
    const float* W1  = (const float*)d_in[2];
    const float* b1  = (const float*)d_in[3];
    const float* W2  = (const float*)d_in[4];
    const float* b2  = (const float*)d_in[5];
    const float* W3  = (const float*)d_in[6];
    const float* b3  = (const float*)d_in[7];
    const float* Wfc = (const float*)d_in[8];
    const float* bfc = (const float*)d_in[9];

    const int Hh = in_sizes[3];            // 64
    const int D  = in_sizes[2] / Hh;       // 128
    const int N  = in_sizes[0] / D;        // 100000
    const int E  = in_sizes[1] / 2;        // 1600000

    float *ht, *bufA, *bufB;
    int* cnt;
    cudaGetSymbolAddress((void**)&ht,   g_ht);
    cudaGetSymbolAddress((void**)&bufA, g_bufA);
    cudaGetSymbolAddress((void**)&bufB, g_bufB);
    cudaGetSymbolAddress((void**)&cnt,  g_cnt);

    const int nb = (N + SCANB - 1) / SCANB;

    // CSR build (zero via memset node -> kernel launch #5 is gemm1 for ncu)
    cudaMemsetAsync(cnt, 0, (size_t)N * sizeof(int));
    hist_kernel<<<(E + 255) / 256, 256>>>(ei, E);
    scan1_kernel<<<nb, SCANB>>>(N);
    scan2_kernel<<<1, 128>>>(nb);
    scan3_kernel<<<(N + 255) / 256, 256>>>(N);
    scatter_csr_kernel<<<(E + 255) / 256, 256>>>(ei, E);

    const int gblocks = (N + 31) / 32;
    const int ablocks = (N * 16 + 255) / 256;

    // layer 1
    gemm_kernel<128, false><<<gblocks, 128>>>(x, W1, ht, N);
    aggregate_kernel<<<ablocks, 256>>>(ht, b1, bufA, N);
    // layer 2
    gemm_kernel<64, true><<<gblocks, 128>>>(bufA, W2, ht, N);
    aggregate_kernel<<<ablocks, 256>>>(ht, b2, bufB, N);
    // layer 3
    gemm_kernel<64, true><<<gblocks, 128>>>(bufB, W3, ht, N);
    aggregate_kernel<<<ablocks, 256>>>(ht, b3, bufA, N);

    // final FC + log_softmax
    fc_kernel<<<(N + 127) / 128, 128>>>(bufA, Wfc, bfc, (float*)d_out, N);
}

// round 6
// speedup vs baseline: 1.2923x; 1.1297x over previous
#include <cuda_runtime.h>
#include <cstdint>
#include <cstdio>

#define HDIM 64

static const int NMAX = 100000;
static const int EMAX = 1600000;
static const int SCANB = 1024;
static const int NBLK = (NMAX + SCANB - 1) / SCANB;   // 98

// ---------------- device scratch (allocation-free rule) ----------------
__device__ __align__(16) int   g_cnt[NMAX];
__device__ __align__(16) int   g_rowptr[NMAX];
__device__ __align__(16) int   g_cursor[NMAX];
__device__ __align__(16) int   g_bsum[NBLK];
__device__ __align__(16) int   g_boff[NBLK];
__device__ __align__(16) float g_dinv[NMAX];
__device__ __align__(16) int   g_csr_src[EMAX];
__device__ __align__(16) float g_csr_norm[EMAX];
__device__ __align__(16) float g_ht[(size_t)NMAX * HDIM];
__device__ __align__(16) float g_bufA[(size_t)NMAX * HDIM];
__device__ __align__(16) float g_bufB[(size_t)NMAX * HDIM];

// ---------------- prep: degree histogram, dinv, scan, CSR scatter ----------------
__global__ void hist_kernel(const int* __restrict__ ei, int E) {
    int e = blockIdx.x * blockDim.x + threadIdx.x;
    if (e >= E) return;
    atomicAdd(&g_cnt[ei[(size_t)E + e]], 1);
}

// block-level inclusive scan -> exclusive partials + block sums; also dinv
__global__ void scan1_kernel(int N) {
    __shared__ int s[SCANB];
    int t = threadIdx.x;
    int i = blockIdx.x * SCANB + t;
    int v = (i < N) ? g_cnt[i] : 0;
    if (i < N) g_dinv[i] = rsqrtf((float)v + 1.0f);  // +1 = self loop
    s[t] = v;
    __syncthreads();
#pragma unroll
    for (int off = 1; off < SCANB; off <<= 1) {
        int a = (t >= off) ? s[t - off] : 0;
        __syncthreads();
        s[t] += a;
        __syncthreads();
    }
    if (i < N) g_rowptr[i] = s[t] - v;   // exclusive
    if (t == SCANB - 1) g_bsum[blockIdx.x] = s[t];
}

// single-block parallel scan of block sums (nb <= 128)
__global__ void scan2_kernel(int nb) {
    __shared__ int s[128];
    int t = threadIdx.x;
    int v = (t < nb) ? g_bsum[t] : 0;
    s[t] = v;
    __syncthreads();
#pragma unroll
    for (int off = 1; off < 128; off <<= 1) {
        int a = (t >= off) ? s[t - off] : 0;
        __syncthreads();
        s[t] += a;
        __syncthreads();
    }
    if (t < nb) g_boff[t] = s[t] - v;    // exclusive
}

__global__ void scan3_kernel(int N) {
    int i = blockIdx.x * blockDim.x + threadIdx.x;
    if (i >= N) return;
    int r = g_rowptr[i] + g_boff[i >> 10];
    g_rowptr[i] = r;
    g_cursor[i] = r;
}

__global__ void scatter_csr_kernel(const int* __restrict__ ei, int E) {
    int e = blockIdx.x * blockDim.x + threadIdx.x;
    if (e >= E) return;
    int s = ei[e];
    int d = ei[(size_t)E + e];
    int pos = atomicAdd(&g_cursor[d], 1);
    g_csr_src[pos]  = s;
    g_csr_norm[pos] = g_dinv[s] * g_dinv[d];
}

// ---------------- GEMM: HT = act(X) @ W  (packed fp32x2 FMA, col-pair form)
// BM=32 rows x 64 cols per block, 128 threads, 4 rows x 8 cols (4 f32x2 pairs) each.
template <int DIN, bool RELU_IN>
__global__ void __launch_bounds__(128) gemm_kernel(const float* __restrict__ X,
                                                   const float* __restrict__ W,
                                                   float* __restrict__ HT,
                                                   int N) {
    __shared__ __align__(16) float Xs[16][32];
    __shared__ __align__(16) float Ws[16][64];

    const int t   = threadIdx.x;      // 0..127
    const int rg  = t >> 4;           // 0..7  (row group of 4)
    const int cg  = t & 15;           // 0..15 (col group of 4)
    const int row0 = blockIdx.x * 32;

    unsigned long long acc2[4][2];
#pragma unroll
    for (int i = 0; i < 4; i++) { acc2[i][0] = 0ull; acc2[i][1] = 0ull; }

    for (int k0 = 0; k0 < DIN; k0 += 16) {
        // load X tile: 32 rows x 16 k (each thread: one float4)
        {
            int r  = t >> 2;          // 0..31
            int kk = (t & 3) * 4;     // 0,4,8,12
            int grow = row0 + r;
            float4 v = make_float4(0.f, 0.f, 0.f, 0.f);
            if (grow < N)
                v = *(const float4*)&X[(size_t)grow * DIN + k0 + kk];
            if (RELU_IN) {
                v.x = fmaxf(v.x, 0.f); v.y = fmaxf(v.y, 0.f);
                v.z = fmaxf(v.z, 0.f); v.w = fmaxf(v.w, 0.f);
            }
            Xs[kk + 0][r] = v.x;
            Xs[kk + 1][r] = v.y;
            Xs[kk + 2][r] = v.z;
            Xs[kk + 3][r] = v.w;
        }
        // load W tile: 16 x 64 floats (each thread: two float4)
        {
#pragma unroll
            for (int i = 0; i < 2; i++) {
                int idx = t + i * 128;        // float4 index, 0..255
                int kk  = idx >> 4;           // 0..15
                int c   = (idx & 15) * 4;     // 0..60
                float4 w = *(const float4*)&W[(size_t)(k0 + kk) * HDIM + c];
                *(float4*)&Ws[kk][c] = w;
            }
        }
        __syncthreads();

#pragma unroll
        for (int kk = 0; kk < 16; kk++) {
            float4 xv = *(const float4*)&Xs[kk][rg * 4];
            ulonglong2 wv = *(const ulonglong2*)&Ws[kk][cg * 4]; // {w0,w1},{w2,w3}
            unsigned int xb[4] = {__float_as_uint(xv.x), __float_as_uint(xv.y),
                                  __float_as_uint(xv.z), __float_as_uint(xv.w)};
#pragma unroll
            for (int i = 0; i < 4; i++) {
                unsigned long long xp;
                asm("mov.b64 %0, {%1, %1};" : "=l"(xp) : "r"(xb[i]));
                asm("fma.rn.f32x2 %0, %1, %2, %0;" : "+l"(acc2[i][0]) : "l"(xp), "l"(wv.x));
                asm("fma.rn.f32x2 %0, %1, %2, %0;" : "+l"(acc2[i][1]) : "l"(xp), "l"(wv.y));
            }
        }
        __syncthreads();
    }

    // epilogue: write HT
#pragma unroll
    for (int i = 0; i < 4; i++) {
        int grow = row0 + rg * 4 + i;
        if (grow < N) {
            unsigned int u0, u1, u2, u3;
            asm("mov.b64 {%0, %1}, %2;" : "=r"(u0), "=r"(u1) : "l"(acc2[i][0]));
            asm("mov.b64 {%0, %1}, %2;" : "=r"(u2), "=r"(u3) : "l"(acc2[i][1]));
            float4 hv = make_float4(__uint_as_float(u0), __uint_as_float(u1),
                                    __uint_as_float(u2), __uint_as_float(u3));
            *(float4*)&HT[(size_t)grow * HDIM + cg * 4] = hv;
        }
    }
}

// ---------------- aggregate: OUT[d] = bias + HT[d]*dinv[d]^2 + sum_e HT[src_e]*norm_e
// 16 threads per node, each owns one float4 of the 64-wide row. (R3 proven form.)
__global__ void aggregate_kernel(const float* __restrict__ HT,
                                 const float* __restrict__ bias,
                                 float* __restrict__ OUT,
                                 int N) {
    int idx  = blockIdx.x * blockDim.x + threadIdx.x;
    int node = idx >> 4;
    int lane = idx & 15;
    if (node >= N) return;

    int start = g_rowptr[node];
    int cnt   = g_cnt[node];

    float4 a0 = make_float4(0.f, 0.f, 0.f, 0.f);
    float4 a1 = make_float4(0.f, 0.f, 0.f, 0.f);

    int i = 0;
    for (; i + 2 <= cnt; i += 2) {
        int e0 = start + i, e1 = start + i + 1;
        int s0 = g_csr_src[e0], s1 = g_csr_src[e1];
        float n0 = g_csr_norm[e0], n1 = g_csr_norm[e1];
        float4 v0 = *(const float4*)&HT[(size_t)s0 * HDIM + lane * 4];
        float4 v1 = *(const float4*)&HT[(size_t)s1 * HDIM + lane * 4];
        a0.x += v0.x * n0; a0.y += v0.y * n0; a0.z += v0.z * n0; a0.w += v0.w * n0;
        a1.x += v1.x * n1; a1.y += v1.y * n1; a1.z += v1.z * n1; a1.w += v1.w * n1;
    }
    if (i < cnt) {
        int e0 = start + i;
        int s0 = g_csr_src[e0];
        float n0 = g_csr_norm[e0];
        float4 v0 = *(const float4*)&HT[(size_t)s0 * HDIM + lane * 4];
        a0.x += v0.x * n0; a0.y += v0.y * n0; a0.z += v0.z * n0; a0.w += v0.w * n0;
    }
    a0.x += a1.x; a0.y += a1.y; a0.z += a1.z; a0.w += a1.w;

    float di = g_dinv[node];
    float d2 = di * di;
    float4 h  = *(const float4*)&HT[(size_t)node * HDIM + lane * 4];
    float4 bb = *(const float4*)&bias[lane * 4];
    float4 o;
    o.x = bb.x + h.x * d2 + a0.x;
    o.y = bb.y + h.y * d2 + a0.y;
    o.z = bb.z + h.z * d2 + a0.z;
    o.w = bb.w + h.w * d2 + a0.w;
    *(float4*)&OUT[(size_t)node * HDIM + lane * 4] = o;
}

// ---------------- final FC (64->2) + log_softmax ----------------
__global__ void fc_kernel(const float* __restrict__ Hin,
                          const float* __restrict__ Wfc,
                          const float* __restrict__ bfc,
                          float* __restrict__ out,
                          int N) {
    __shared__ float Wf[HDIM * 2];
    __shared__ float bf[2];
    if (threadIdx.x < HDIM * 2) Wf[threadIdx.x] = Wfc[threadIdx.x];
    if (threadIdx.x < 2) bf[threadIdx.x] = bfc[threadIdx.x];
    __syncthreads();

    int n = blockIdx.x * blockDim.x + threadIdx.x;
    if (n >= N) return;

    float l0 = bf[0], l1 = bf[1];
    const float4* hp = (const float4*)&Hin[(size_t)n * HDIM];
#pragma unroll
    for (int k4 = 0; k4 < HDIM / 4; k4++) {
        float4 h = hp[k4];
        float h0 = fmaxf(h.x, 0.f), h1 = fmaxf(h.y, 0.f);
        float h2 = fmaxf(h.z, 0.f), h3 = fmaxf(h.w, 0.f);
        int k = k4 * 4;
        l0 += h0 * Wf[(k + 0) * 2 + 0] + h1 * Wf[(k + 1) * 2 + 0] +
              h2 * Wf[(k + 2) * 2 + 0] + h3 * Wf[(k + 3) * 2 + 0];
        l1 += h0 * Wf[(k + 0) * 2 + 1] + h1 * Wf[(k + 1) * 2 + 1] +
              h2 * Wf[(k + 2) * 2 + 1] + h3 * Wf[(k + 3) * 2 + 1];
    }
    float m = fmaxf(l0, l1);
    float lse = m + logf(expf(l0 - m) + expf(l1 - m));
    out[(size_t)n * 2 + 0] = l0 - lse;
    out[(size_t)n * 2 + 1] = l1 - lse;
}

// ---------------- launch ----------------
extern "C" void kernel_launch(void* const* d_in, const int* in_sizes, int n_in,
                              void* d_out, int out_size) {
    const float* x   = (const float*)d_in[0];
    const int*   ei  = (const int*)d_in[1];   // int32 (JAX x64 disabled)
    const float* W1  = (const float*)d_in[2];
    const float* b1  = (const float*)d_in[3];
    const float* W2  = (const float*)d_in[4];
    const float* b2  = (const float*)d_in[5];
    const float* W3  = (const float*)d_in[6];
    const float* b3  = (const float*)d_in[7];
    const float* Wfc = (const float*)d_in[8];
    const float* bfc = (const float*)d_in[9];

    const int Hh = in_sizes[3];            // 64
    const int D  = in_sizes[2] / Hh;       // 128
    const int N  = in_sizes[0] / D;        // 100000
    const int E  = in_sizes[1] / 2;        // 1600000

    float *ht, *bufA, *bufB;
    int* cnt;
    cudaGetSymbolAddress((void**)&ht,   g_ht);
    cudaGetSymbolAddress((void**)&bufA, g_bufA);
    cudaGetSymbolAddress((void**)&bufB, g_bufB);
    cudaGetSymbolAddress((void**)&cnt,  g_cnt);

    const int nb = (N + SCANB - 1) / SCANB;
    const int gblocks = (N + 31) / 32;
    const int ablocks = (N * 16 + 255) / 256;

    // CSR build, with gemm1 interleaved at kernel slot #4 so ncu captures it.
    cudaMemsetAsync(cnt, 0, (size_t)N * sizeof(int));
    hist_kernel<<<(E + 255) / 256, 256>>>(ei, E);                 // #1
    scan1_kernel<<<nb, SCANB>>>(N);                               // #2
    scan2_kernel<<<1, 128>>>(nb);                                 // #3
    gemm_kernel<128, false><<<gblocks, 128>>>(x, W1, ht, N);      // #4 (ncu slot)
    scan3_kernel<<<(N + 255) / 256, 256>>>(N);                    // #5
    scatter_csr_kernel<<<(E + 255) / 256, 256>>>(ei, E);          // #6

    // layer 1 aggregate
    aggregate_kernel<<<ablocks, 256>>>(ht, b1, bufA, N);
    // layer 2
    gemm_kernel<64, true><<<gblocks, 128>>>(bufA, W2, ht, N);
    aggregate_kernel<<<ablocks, 256>>>(ht, b2, bufB, N);
    // layer 3
    gemm_kernel<64, true><<<gblocks, 128>>>(bufB, W3, ht, N);
    aggregate_kernel<<<ablocks, 256>>>(ht, b3, bufA, N);

    // final FC + log_softmax
    fc_kernel<<<(N + 127) / 128, 128>>>(bufA, Wfc, bfc, (float*)d_out, N);
}